// round 2
// baseline (speedup 1.0000x reference)
#include <cuda_runtime.h>
#include <stdint.h>

typedef unsigned long long u64;

#define BB 2
#define KK 19
#define BKT 38
#define MM 1024
#define CC 256
#define NP 128
#define NS 128
#define FS (KK*MM)

// ---------------- device scratch ----------------
__device__ float g_x[BKT*MM*3];
__device__ float g_F1[BKT*MM*128];
__device__ float g_newxyz[BKT*NP*3];
__device__ int   g_gidx[BKT*NP*NS];
__device__ float g_feat[BKT*128*NP];
__device__ float g_net[BKT*128*NP];
__device__ float g_W1T[CC*128];
__device__ float g_W2T[128*128];
__device__ float g_W3T[128*128];
__device__ float g_C1T[128*128];
__device__ float g_C2T[128*128];
__device__ float g_W1x[3*128];
__device__ float g_bM1[128], g_bM2[128], g_bM3[128], g_bC1[128], g_bC2[128];

// ---------------- f32x2 helpers ----------------
__device__ __forceinline__ u64 pk2(float a){ u64 r; asm("mov.b64 %0, {%1, %1};" : "=l"(r) : "f"(a)); return r; }
__device__ __forceinline__ void fma2(u64& d, u64 a, u64 b){ asm("fma.rn.f32x2 %0, %1, %2, %0;" : "+l"(d) : "l"(a), "l"(b)); }
__device__ __forceinline__ float2 upk(u64 v){ float2 r; asm("mov.b64 {%0, %1}, %2;" : "=f"(r.x), "=f"(r.y) : "l"(v)); return r; }

__device__ __forceinline__ void zacc(u64 acc[8][4]){
#pragma unroll
  for (int i=0;i<8;i++)
#pragma unroll
    for (int j=0;j<4;j++) acc[i][j]=0ull;
}

#define GROW(i, av) { u64 a_=pk2(av); fma2(acc[i][0],a_,b0); fma2(acc[i][1],a_,b1); fma2(acc[i][2],a_,b2); fma2(acc[i][3],a_,b3); }

template<int KC>
__device__ __forceinline__ void gemm8x8(const float* sA, const float* sB, u64 acc[8][4], int s0, int o0){
#pragma unroll 4
  for (int c = 0; c < KC; c++){
    float4 a0 = *(const float4*)(sA + c*128 + s0);
    float4 a1 = *(const float4*)(sA + c*128 + s0 + 4);
    const u64* bp = (const u64*)(sB + c*128 + o0);
    u64 b0=bp[0], b1=bp[1], b2=bp[2], b3=bp[3];
    GROW(0,a0.x) GROW(1,a0.y) GROW(2,a0.z) GROW(3,a0.w)
    GROW(4,a1.x) GROW(5,a1.y) GROW(6,a1.z) GROW(7,a1.w)
  }
}

// exact (no-fma) squared distance to match JAX comparisons bit-for-bit
__device__ __forceinline__ float d2f(float ax,float ay,float az,float bx,float by,float bz){
  float dx=__fsub_rn(ax,bx), dy=__fsub_rn(ay,by), dz=__fsub_rn(az,bz);
  return __fadd_rn(__fadd_rn(__fmul_rn(dx,dx),__fmul_rn(dy,dy)),__fmul_rn(dz,dz));
}

// ---------------- prep / fold ----------------
__global__ void k_prep_x(const float* __restrict__ xyz){
  int i = blockIdx.x*256 + threadIdx.x;
  if (i >= BKT*MM*3) return;
  int j = i % 3, rest = i / 3;
  int m = rest % MM, bk = rest / MM;
  int b = bk / KK, k = bk % KK;
  g_x[i] = xyz[((size_t)(b*MM + m)*KK + k)*3 + j];
}

__global__ void k_foldT(int which, const float* __restrict__ w, const float* __restrict__ g,
                        int Cdim, int Cfull, int coff){
  float* dst = which==0?g_W1T: which==1?g_W2T: which==2?g_W3T: which==3?g_C1T: g_C2T;
  int i = blockIdx.x*256 + threadIdx.x;
  if (i >= Cdim*128) return;
  int c = i >> 7, o = i & 127;
  dst[i] = w[o*Cfull + coff + c] * __fdiv_rn(g[o], sqrtf(1.0f + 1e-5f));
}

__global__ void k_foldB(int which, const float* __restrict__ b, const float* __restrict__ g,
                        const float* __restrict__ be){
  float* dst = which==0?g_bM1: which==1?g_bM2: which==2?g_bM3: which==3?g_bC1: g_bC2;
  int o = threadIdx.x;
  float gp = __fdiv_rn(g[o], sqrtf(1.0f + 1e-5f));
  dst[o] = b[o]*gp + be[o];
}

__global__ void k_foldWx(const float* __restrict__ w, const float* __restrict__ g){
  int i = blockIdx.x*256 + threadIdx.x;
  if (i >= 3*128) return;
  int j = i >> 7, o = i & 127;
  g_W1x[i] = w[o*259 + j] * __fdiv_rn(g[o], sqrtf(1.0f + 1e-5f));
}

// ---------------- FPS ----------------
__global__ __launch_bounds__(1024) void k_fps(float* __restrict__ outAgg){
  int bk = blockIdx.x, t = threadIdx.x;
  const float* xb = g_x + bk*MM*3;
  float px = xb[t*3], py = xb[t*3+1], pz = xb[t*3+2];
  float dist = 1e10f;
  __shared__ float sc[3]; __shared__ float sv[32]; __shared__ int sw_[32]; __shared__ int sfar;
  if (t == 0) sfar = 0;
  __syncthreads();
  int lane = t & 31, wp = t >> 5;
  for (int i = 0; i < NP; i++){
    if (t == 0){
      int f = sfar;
      float cx = xb[f*3], cy = xb[f*3+1], cz = xb[f*3+2];
      sc[0]=cx; sc[1]=cy; sc[2]=cz;
      float* nz = g_newxyz + (bk*NP+i)*3; nz[0]=cx; nz[1]=cy; nz[2]=cz;
      float* oa = outAgg + (bk*NP+i)*3;   oa[0]=cx; oa[1]=cy; oa[2]=cz;
    }
    __syncthreads();
    float d = d2f(px,py,pz, sc[0],sc[1],sc[2]);
    dist = fminf(dist, d);
    float v = dist; int ix = t;
#pragma unroll
    for (int off=16; off; off>>=1){
      float ov = __shfl_down_sync(0xffffffffu, v, off);
      int   oi = __shfl_down_sync(0xffffffffu, ix, off);
      if (ov > v || (ov == v && oi < ix)){ v = ov; ix = oi; }
    }
    if (lane == 0){ sv[wp] = v; sw_[wp] = ix; }
    __syncthreads();
    if (t < 32){
      v = sv[t]; ix = sw_[t];
#pragma unroll
      for (int off=16; off; off>>=1){
        float ov = __shfl_down_sync(0xffffffffu, v, off);
        int   oi = __shfl_down_sync(0xffffffffu, ix, off);
        if (ov > v || (ov == v && oi < ix)){ v = ov; ix = oi; }
      }
      if (t == 0) sfar = ix;
    }
    __syncthreads();
  }
}

// ---------------- ball query: one warp per (bk,p) ----------------
__global__ void k_ball(){
  int w = (blockIdx.x*blockDim.x + threadIdx.x) >> 5;
  int lane = threadIdx.x & 31;
  if (w >= BKT*NP) return;
  int bk = w / NP;
  const float* ctr = g_newxyz + w*3;
  float cx=ctr[0], cy=ctr[1], cz=ctr[2];
  const float R2 = (float)(0.15*0.15);
  int base = w*NS;
  int cnt = 0, first = 0;
  for (int ch = 0; ch < MM/32; ch++){
    int m = ch*32 + lane;
    const float* xp = g_x + (bk*MM + m)*3;
    float d = d2f(cx,cy,cz, xp[0],xp[1],xp[2]);
    unsigned mask = __ballot_sync(0xffffffffu, d < R2);
    if (cnt == 0 && mask) first = ch*32 + __ffs(mask) - 1;
    int pos = cnt + __popc(mask & ((1u<<lane)-1u));
    if ((d < R2) && pos < NS) g_gidx[base + pos] = m;
    cnt += __popc(mask);
    if (cnt >= NS) break;
  }
  for (int j = cnt + lane; j < NS; j += 32) g_gidx[base + j] = first;
}

// ---------------- F1 = (folded W1_feat) @ f  per point ----------------
__global__ __launch_bounds__(256) void k_f1(const float* __restrict__ features){
  extern __shared__ float sm[];
  float* sF = sm;            // 64 x 128
  float* sW = sm + 64*128;   // 64 x 128
  int bk = blockIdx.y, mb = blockIdx.x*128;
  int b = bk / KK, k = bk % KK;
  int t = threadIdx.x;
  int s0 = (t & 15)*8, o0 = (t >> 4)*8;
  u64 acc[8][4]; zacc(acc);
  for (int c0 = 0; c0 < CC; c0 += 64){
    // load f tile [64 c][128 m]
#pragma unroll
    for (int r = 0; r < 8; r++){
      int e4 = r*256 + t;            // float4 index, 2048 total
      int ci = e4 >> 5, mi4 = e4 & 31;
      ((float4*)sF)[e4] = *(const float4*)(features + ((size_t)(b*CC + c0 + ci)*KK + k)*MM + mb + mi4*4);
    }
#pragma unroll
    for (int r = 0; r < 8; r++){
      int e4 = r*256 + t;
      ((float4*)sW)[e4] = ((const float4*)(g_W1T + c0*128))[e4];
    }
    __syncthreads();
    gemm8x8<64>(sF, sW, acc, s0, o0);
    __syncthreads();
  }
#pragma unroll
  for (int si = 0; si < 8; si++){
    size_t row = (size_t)bk*MM + mb + s0 + si;
#pragma unroll
    for (int j = 0; j < 4; j++)
      *(float2*)(g_F1 + row*128 + o0 + 2*j) = upk(acc[si][j]);
  }
}

// ---------------- group kernel: layer1 gather + layers 2,3 + maxpool ----------------
__global__ __launch_bounds__(256) void k_group(float* __restrict__ outFeat){
  extern __shared__ float sm[];
  float* sH = sm;            // 128 x 128
  float* sW = sm + 16384;    // 128 x 128 (also pm buffer)
  __shared__ int   sIdx[NS];
  __shared__ float sCtr[3];
  __shared__ float sWx[3*128];
  __shared__ float sB1[128];
  int bk = blockIdx.y, p = blockIdx.x;
  int t = threadIdx.x;
  int gp_ = (bk*NP + p);
  if (t < NS) sIdx[t] = g_gidx[gp_*NS + t];
  if (t < 3)  sCtr[t] = g_newxyz[gp_*3 + t];
  if (t < 128){ sWx[t]=g_W1x[t]; sWx[128+t]=g_W1x[128+t]; sWx[256+t]=g_W1x[256+t]; sB1[t]=g_bM1[t]; }
  __syncthreads();
  // ---- layer 1 build: sH[o][s] ----
  {
    int s = t >> 1, half = t & 1, ob = half*64;
    int m = sIdx[s];
    const float* xp = g_x + (bk*MM + m)*3;
    float gx = __fdiv_rn(__fsub_rn(xp[0], sCtr[0]), 0.15f);
    float gy = __fdiv_rn(__fsub_rn(xp[1], sCtr[1]), 0.15f);
    float gz = __fdiv_rn(__fsub_rn(xp[2], sCtr[2]), 0.15f);
    const float4* fp = (const float4*)(g_F1 + ((size_t)bk*MM + m)*128 + ob);
#pragma unroll 4
    for (int j4 = 0; j4 < 16; j4++){
      float4 fv = fp[j4];
      int o = ob + j4*4;
      float v0 = fv.x + sWx[o]*gx   + sWx[128+o]*gy   + sWx[256+o]*gz   + sB1[o];
      float v1 = fv.y + sWx[o+1]*gx + sWx[128+o+1]*gy + sWx[256+o+1]*gz + sB1[o+1];
      float v2 = fv.z + sWx[o+2]*gx + sWx[128+o+2]*gy + sWx[256+o+2]*gz + sB1[o+2];
      float v3 = fv.w + sWx[o+3]*gx + sWx[128+o+3]*gy + sWx[256+o+3]*gz + sB1[o+3];
      sH[(o)*128+s]   = fmaxf(v0, 0.f);
      sH[(o+1)*128+s] = fmaxf(v1, 0.f);
      sH[(o+2)*128+s] = fmaxf(v2, 0.f);
      sH[(o+3)*128+s] = fmaxf(v3, 0.f);
    }
  }
  // load W2
#pragma unroll
  for (int r = 0; r < 16; r++) ((float4*)sW)[r*256 + t] = ((const float4*)g_W2T)[r*256 + t];
  __syncthreads();
  int s0 = (t & 15)*8, o0 = (t >> 4)*8;
  u64 acc[8][4]; zacc(acc);
  gemm8x8<128>(sH, sW, acc, s0, o0);
  // ---- layer2 epilogue ----
  float2 bb[4];
#pragma unroll
  for (int j = 0; j < 4; j++) bb[j] = *(const float2*)(g_bM2 + o0 + 2*j);
  __syncthreads();
#pragma unroll
  for (int si = 0; si < 8; si++)
#pragma unroll
    for (int j = 0; j < 4; j++){
      float2 v = upk(acc[si][j]);
      sH[(o0+2*j)*128 + s0+si]   = fmaxf(v.x + bb[j].x, 0.f);
      sH[(o0+2*j+1)*128 + s0+si] = fmaxf(v.y + bb[j].y, 0.f);
    }
#pragma unroll
  for (int r = 0; r < 16; r++) ((float4*)sW)[r*256 + t] = ((const float4*)g_W3T)[r*256 + t];
  __syncthreads();
  zacc(acc);
  gemm8x8<128>(sH, sW, acc, s0, o0);
  // ---- layer3 + maxpool ----
#pragma unroll
  for (int j = 0; j < 4; j++) bb[j] = *(const float2*)(g_bM3 + o0 + 2*j);
  float lm[8];
#pragma unroll
  for (int oi = 0; oi < 8; oi++) lm[oi] = 0.f;
#pragma unroll
  for (int si = 0; si < 8; si++)
#pragma unroll
    for (int j = 0; j < 4; j++){
      float2 v = upk(acc[si][j]);
      lm[2*j]   = fmaxf(lm[2*j],   fmaxf(v.x + bb[j].x, 0.f));
      lm[2*j+1] = fmaxf(lm[2*j+1], fmaxf(v.y + bb[j].y, 0.f));
    }
  __syncthreads();                 // sW free now
  float* pm = sW;                  // [16 ogroups][16 sgroups][8]
#pragma unroll
  for (int oi = 0; oi < 8; oi++) pm[((t>>4)*16 + (t&15))*8 + oi] = lm[oi];
  __syncthreads();
  if (t < 128){
    int og = t >> 3, oi = t & 7;
    float mx = pm[(og*16)*8 + oi];
#pragma unroll
    for (int r = 1; r < 16; r++) mx = fmaxf(mx, pm[(og*16 + r)*8 + oi]);
    int fo = (bk*128 + t)*NP + p;
    g_feat[fo] = mx;
    outFeat[fo] = mx;
  }
}

// ---------------- c1, c2 ----------------
__global__ __launch_bounds__(256) void k_c12(){
  extern __shared__ float sm[];
  float* sH = sm;
  float* sW = sm + 16384;
  int bk = blockIdx.x, t = threadIdx.x;
#pragma unroll
  for (int r = 0; r < 16; r++){
    ((float4*)sH)[r*256 + t] = ((const float4*)(g_feat + bk*16384))[r*256 + t];
    ((float4*)sW)[r*256 + t] = ((const float4*)g_C1T)[r*256 + t];
  }
  __syncthreads();
  int s0 = (t & 15)*8, o0 = (t >> 4)*8;
  u64 acc[8][4]; zacc(acc);
  gemm8x8<128>(sH, sW, acc, s0, o0);
  float2 bb[4];
#pragma unroll
  for (int j = 0; j < 4; j++) bb[j] = *(const float2*)(g_bC1 + o0 + 2*j);
  __syncthreads();
#pragma unroll
  for (int si = 0; si < 8; si++)
#pragma unroll
    for (int j = 0; j < 4; j++){
      float2 v = upk(acc[si][j]);
      sH[(o0+2*j)*128 + s0+si]   = fmaxf(v.x + bb[j].x, 0.f);
      sH[(o0+2*j+1)*128 + s0+si] = fmaxf(v.y + bb[j].y, 0.f);
    }
#pragma unroll
  for (int r = 0; r < 16; r++) ((float4*)sW)[r*256 + t] = ((const float4*)g_C2T)[r*256 + t];
  __syncthreads();
  zacc(acc);
  gemm8x8<128>(sH, sW, acc, s0, o0);
#pragma unroll
  for (int j = 0; j < 4; j++) bb[j] = *(const float2*)(g_bC2 + o0 + 2*j);
  __syncthreads();
#pragma unroll
  for (int si = 0; si < 8; si++)
#pragma unroll
    for (int j = 0; j < 4; j++){
      float2 v = upk(acc[si][j]);
      sH[(o0+2*j)*128 + s0+si]   = fmaxf(v.x + bb[j].x, 0.f);
      sH[(o0+2*j+1)*128 + s0+si] = fmaxf(v.y + bb[j].y, 0.f);
    }
  __syncthreads();
#pragma unroll
  for (int r = 0; r < 16; r++) ((float4*)(g_net + bk*16384))[r*256 + t] = ((const float4*)sH)[r*256 + t];
}

// ---------------- head ----------------
__global__ void k_head(const float* __restrict__ opw, const float* __restrict__ opb,
                       float* __restrict__ outScores){
  __shared__ float sOp[5*128]; __shared__ float sOb[5];
  int bk = blockIdx.x, k = bk % KK, t = threadIdx.x;
  for (int i = t; i < 640; i += 128) sOp[i] = opw[k*640 + i];
  if (t < 5) sOb[t] = opb[k*5 + t];
  __syncthreads();
  float a0=0,a1=0,a2=0,a3=0,a4=0;
  const float* nb = g_net + bk*16384 + t;
#pragma unroll 4
  for (int c = 0; c < 128; c++){
    float nv = nb[c*128];
    a0 += sOp[c]*nv; a1 += sOp[128+c]*nv; a2 += sOp[256+c]*nv; a3 += sOp[384+c]*nv; a4 += sOp[512+c]*nv;
  }
  a0+=sOb[0]; a1+=sOb[1]; a2+=sOb[2]; a3+=sOb[3]; a4+=sOb[4];
  const float* nz = g_newxyz + (bk*NP + t)*3;
  float* o = outScores + (bk*NP + t)*5;
  o[0]=a0; o[1]=a1; o[2]=nz[0]+a2; o[3]=nz[1]+a3; o[4]=nz[2]+a4;
}

// ---------------- launcher ----------------
extern "C" void kernel_launch(void* const* d_in, const int* in_sizes, int n_in,
                              void* d_out, int out_size){
  (void)in_sizes; (void)n_in; (void)out_size;
  const float* xyz  = (const float*)d_in[0];
  const float* feats= (const float*)d_in[1];
  const float* m1_w = (const float*)d_in[2];
  const float* m1_b = (const float*)d_in[3];
  const float* m1_g = (const float*)d_in[4];
  const float* m1_be= (const float*)d_in[5];
  const float* m2_w = (const float*)d_in[6];
  const float* m2_b = (const float*)d_in[7];
  const float* m2_g = (const float*)d_in[8];
  const float* m2_be= (const float*)d_in[9];
  const float* m3_w = (const float*)d_in[10];
  const float* m3_b = (const float*)d_in[11];
  const float* m3_g = (const float*)d_in[12];
  const float* m3_be= (const float*)d_in[13];
  const float* c1_w = (const float*)d_in[14];
  const float* c1_b = (const float*)d_in[15];
  const float* c1_g = (const float*)d_in[16];
  const float* c1_be= (const float*)d_in[17];
  const float* c2_w = (const float*)d_in[18];
  const float* c2_b = (const float*)d_in[19];
  const float* c2_g = (const float*)d_in[20];
  const float* c2_be= (const float*)d_in[21];
  const float* op_w = (const float*)d_in[22];
  const float* op_b = (const float*)d_in[23];

  float* out = (float*)d_out;
  float* outScores = out;                 // 38*128*5 = 24320
  float* outAgg    = out + 24320;         // 38*128*3 = 14592
  float* outFeat   = out + 38912;         // 38*128*128 = 622592

  cudaFuncSetAttribute(k_f1,    cudaFuncAttributeMaxDynamicSharedMemorySize, 65536);
  cudaFuncSetAttribute(k_group, cudaFuncAttributeMaxDynamicSharedMemorySize, 131072);
  cudaFuncSetAttribute(k_c12,   cudaFuncAttributeMaxDynamicSharedMemorySize, 131072);

  k_prep_x<<<(BKT*MM*3 + 255)/256, 256>>>(xyz);
  k_foldT<<<(CC*128 + 255)/256, 256>>>(0, m1_w, m1_g, CC, 259, 3);
  k_foldT<<<64, 256>>>(1, m2_w, m2_g, 128, 128, 0);
  k_foldT<<<64, 256>>>(2, m3_w, m3_g, 128, 128, 0);
  k_foldT<<<64, 256>>>(3, c1_w, c1_g, 128, 128, 0);
  k_foldT<<<64, 256>>>(4, c2_w, c2_g, 128, 128, 0);
  k_foldB<<<1, 128>>>(0, m1_b, m1_g, m1_be);
  k_foldB<<<1, 128>>>(1, m2_b, m2_g, m2_be);
  k_foldB<<<1, 128>>>(2, m3_b, m3_g, m3_be);
  k_foldB<<<1, 128>>>(3, c1_b, c1_g, c1_be);
  k_foldB<<<1, 128>>>(4, c2_b, c2_g, c2_be);
  k_foldWx<<<2, 256>>>(m1_w, m1_g);

  k_fps<<<BKT, 1024>>>(outAgg);
  k_f1<<<dim3(MM/128, BKT), 256, 65536>>>(feats);
  k_ball<<<(BKT*NP*32 + 255)/256, 256>>>();
  k_group<<<dim3(NP, BKT), 256, 131072>>>(outFeat);
  k_c12<<<BKT, 256, 131072>>>();
  k_head<<<BKT, 128>>>(op_w, op_b, outScores);
}

// round 6
// speedup vs baseline: 1.7923x; 1.7923x over previous
#include <cuda_runtime.h>
#include <stdint.h>

typedef unsigned long long u64;
typedef uint32_t u32;

#define BB 2
#define KK 19
#define BKT 38
#define MM 1024
#define CC 256
#define NP 128
#define NS 128

// ---------------- device scratch ----------------
__device__ float g_x[BKT*MM*3];
__device__ float g_F1[BKT*MM*128];
__device__ float g_newxyz[BKT*NP*3];
__device__ int   g_gidx[BKT*NP*NS];
__device__ float g_feat[BKT*128*NP];
__device__ float g_net[BKT*128*NP];
__device__ float g_W1T[CC*128];      // [c][o] fp32 (FFMA2 k_f1)
__device__ float g_W2T[128*128];     // [o][c] tf32-rounded (mma B operand)
__device__ float g_W3T[128*128];     // [o][c] tf32-rounded
__device__ float g_C1T[128*128];     // [c][o] fp32
__device__ float g_C2T[128*128];
__device__ float g_W1x[3*128];
__device__ float g_bM1[128], g_bM2[128], g_bM3[128], g_bC1[128], g_bC2[128];

// ---------------- tf32 helpers ----------------
__device__ __forceinline__ u32 tf32b(float f){
  u32 r; asm("cvt.rna.tf32.f32 %0, %1;" : "=r"(r) : "f"(f)); return r;
}
__device__ __forceinline__ float tf32r(float f){ return __uint_as_float(tf32b(f)); }

__device__ __forceinline__ void mma_tf32(float d[4], const u32 a[4], const u32 b[2]){
  asm volatile("mma.sync.aligned.m16n8k8.row.col.f32.tf32.tf32.f32 "
    "{%0,%1,%2,%3}, {%4,%5,%6,%7}, {%8,%9}, {%0,%1,%2,%3};"
    : "+f"(d[0]), "+f"(d[1]), "+f"(d[2]), "+f"(d[3])
    : "r"(a[0]), "r"(a[1]), "r"(a[2]), "r"(a[3]), "r"(b[0]), "r"(b[1]));
}

// ---------------- f32x2 helpers (k_f1 / k_c12) ----------------
__device__ __forceinline__ u64 pk2(float a){ u64 r; asm("mov.b64 %0, {%1, %1};" : "=l"(r) : "f"(a)); return r; }
__device__ __forceinline__ void fma2(u64& d, u64 a, u64 b){ asm("fma.rn.f32x2 %0, %1, %2, %0;" : "+l"(d) : "l"(a), "l"(b)); }
__device__ __forceinline__ float2 upk(u64 v){ float2 r; asm("mov.b64 {%0, %1}, %2;" : "=f"(r.x), "=f"(r.y) : "l"(v)); return r; }
__device__ __forceinline__ void zacc(u64 acc[8][4]){
#pragma unroll
  for (int i=0;i<8;i++)
#pragma unroll
    for (int j=0;j<4;j++) acc[i][j]=0ull;
}
#define GROW(i, av) { u64 a_=pk2(av); fma2(acc[i][0],a_,b0); fma2(acc[i][1],a_,b1); fma2(acc[i][2],a_,b2); fma2(acc[i][3],a_,b3); }
template<int KC>
__device__ __forceinline__ void gemm8x8(const float* sA, const float* sB, u64 acc[8][4], int s0, int o0){
#pragma unroll 4
  for (int c = 0; c < KC; c++){
    float4 a0 = *(const float4*)(sA + c*128 + s0);
    float4 a1 = *(const float4*)(sA + c*128 + s0 + 4);
    const u64* bp = (const u64*)(sB + c*128 + o0);
    u64 b0=bp[0], b1=bp[1], b2=bp[2], b3=bp[3];
    GROW(0,a0.x) GROW(1,a0.y) GROW(2,a0.z) GROW(3,a0.w)
    GROW(4,a1.x) GROW(5,a1.y) GROW(6,a1.z) GROW(7,a1.w)
  }
}

__device__ __forceinline__ float d2f(float ax,float ay,float az,float bx,float by,float bz){
  float dx=__fsub_rn(ax,bx), dy=__fsub_rn(ay,by), dz=__fsub_rn(az,bz);
  return __fadd_rn(__fadd_rn(__fmul_rn(dx,dx),__fmul_rn(dy,dy)),__fmul_rn(dz,dz));
}

// ---------------- launch 0: prep x ----------------
__global__ void k_prep_x(const float* __restrict__ xyz){
  int i = blockIdx.x*256 + threadIdx.x;
  if (i >= BKT*MM*3) return;
  int j = i % 3, rest = i / 3;
  int m = rest % MM, bk = rest / MM;
  int b = bk / KK, k = bk % KK;
  g_x[i] = xyz[((size_t)(b*MM + m)*KK + k)*3 + j];
}

// ---------------- launch 1: fold everything ----------------
__device__ __forceinline__ float gpv(float g){ return __fdiv_rn(g, sqrtf(1.0f + 1e-5f)); }

__global__ void k_fold_all(const float* m1w, const float* m1g,
                           const float* m2w, const float* m2g,
                           const float* m3w, const float* m3g,
                           const float* c1w, const float* c1g,
                           const float* c2w, const float* c2g,
                           const float* m1b, const float* m1be,
                           const float* m2b, const float* m2be,
                           const float* m3b, const float* m3be,
                           const float* c1b, const float* c1be,
                           const float* c2b, const float* c2be){
  int i = blockIdx.x*256 + threadIdx.x;
  if (i < 32768){                 // W1T [c][o]
    int c = i>>7, o = i&127;
    g_W1T[i] = m1w[o*259 + 3 + c] * gpv(m1g[o]);
    return;
  } i -= 32768;
  if (i < 16384){                 // W2T [o][c] tf32-rounded
    g_W2T[i] = tf32r(m2w[i] * gpv(m2g[i>>7]));
    return;
  } i -= 16384;
  if (i < 16384){
    g_W3T[i] = tf32r(m3w[i] * gpv(m3g[i>>7]));
    return;
  } i -= 16384;
  if (i < 16384){                 // C1T [c][o]
    int c = i>>7, o = i&127;
    g_C1T[i] = c1w[o*128+c] * gpv(c1g[o]);
    return;
  } i -= 16384;
  if (i < 16384){
    int c = i>>7, o = i&127;
    g_C2T[i] = c2w[o*128+c] * gpv(c2g[o]);
    return;
  } i -= 16384;
  if (i < 640){                   // biases
    int which = i>>7, o = i&127;
    const float* b  = which==0?m1b: which==1?m2b: which==2?m3b: which==3?c1b:c2b;
    const float* g  = which==0?m1g: which==1?m2g: which==2?m3g: which==3?c1g:c2g;
    const float* be = which==0?m1be:which==1?m2be:which==2?m3be:which==3?c1be:c2be;
    float* dst = which==0?g_bM1: which==1?g_bM2: which==2?g_bM3: which==3?g_bC1:g_bC2;
    dst[o] = b[o]*gpv(g[o]) + be[o];
    return;
  } i -= 640;
  if (i < 384){                   // W1x
    int j = i>>7, o = i&127;
    g_W1x[i] = m1w[o*259 + j] * gpv(m1g[o]);
  }
}

// ---------------- launch 2: FPS ----------------
__global__ __launch_bounds__(1024) void k_fps(float* __restrict__ outAgg){
  int bk = blockIdx.x, t = threadIdx.x;
  const float* xb = g_x + bk*MM*3;
  float px = xb[t*3], py = xb[t*3+1], pz = xb[t*3+2];
  float dist = 1e10f;
  __shared__ float sc[3]; __shared__ float sv[32]; __shared__ int sw_[32]; __shared__ int sfar;
  if (t == 0) sfar = 0;
  __syncthreads();
  int lane = t & 31, wp = t >> 5;
  for (int i = 0; i < NP; i++){
    if (t == 0){
      int f = sfar;
      float cx = xb[f*3], cy = xb[f*3+1], cz = xb[f*3+2];
      sc[0]=cx; sc[1]=cy; sc[2]=cz;
      float* nz = g_newxyz + (bk*NP+i)*3; nz[0]=cx; nz[1]=cy; nz[2]=cz;
      float* oa = outAgg + (bk*NP+i)*3;   oa[0]=cx; oa[1]=cy; oa[2]=cz;
    }
    __syncthreads();
    float d = d2f(px,py,pz, sc[0],sc[1],sc[2]);
    dist = fminf(dist, d);
    float v = dist; int ix = t;
#pragma unroll
    for (int off=16; off; off>>=1){
      float ov = __shfl_down_sync(0xffffffffu, v, off);
      int   oi = __shfl_down_sync(0xffffffffu, ix, off);
      if (ov > v || (ov == v && oi < ix)){ v = ov; ix = oi; }
    }
    if (lane == 0){ sv[wp] = v; sw_[wp] = ix; }
    __syncthreads();
    if (t < 32){
      v = sv[t]; ix = sw_[t];
#pragma unroll
      for (int off=16; off; off>>=1){
        float ov = __shfl_down_sync(0xffffffffu, v, off);
        int   oi = __shfl_down_sync(0xffffffffu, ix, off);
        if (ov > v || (ov == v && oi < ix)){ v = ov; ix = oi; }
      }
      if (t == 0) sfar = ix;
    }
    __syncthreads();
  }
}

// ---------------- launch 3: F1 per point ----------------
__global__ __launch_bounds__(256) void k_f1(const float* __restrict__ features){
  extern __shared__ float sm[];
  float* sF = sm;
  float* sW = sm + 64*128;
  int bk = blockIdx.y, mb = blockIdx.x*128;
  int b = bk / KK, k = bk % KK;
  int t = threadIdx.x;
  int s0 = (t & 15)*8, o0 = (t >> 4)*8;
  u64 acc[8][4]; zacc(acc);
  for (int c0 = 0; c0 < CC; c0 += 64){
#pragma unroll
    for (int r = 0; r < 8; r++){
      int e4 = r*256 + t;
      int ci = e4 >> 5, mi4 = e4 & 31;
      ((float4*)sF)[e4] = *(const float4*)(features + ((size_t)(b*CC + c0 + ci)*KK + k)*MM + mb + mi4*4);
    }
#pragma unroll
    for (int r = 0; r < 8; r++){
      int e4 = r*256 + t;
      ((float4*)sW)[e4] = ((const float4*)(g_W1T + c0*128))[e4];
    }
    __syncthreads();
    gemm8x8<64>(sF, sW, acc, s0, o0);
    __syncthreads();
  }
#pragma unroll
  for (int si = 0; si < 8; si++){
    size_t row = (size_t)bk*MM + mb + s0 + si;
#pragma unroll
    for (int j = 0; j < 4; j++)
      *(float2*)(g_F1 + row*128 + o0 + 2*j) = upk(acc[si][j]);
  }
}

// ---------------- launch 4: ball query ----------------
__global__ void k_ball(){
  int w = (blockIdx.x*blockDim.x + threadIdx.x) >> 5;
  int lane = threadIdx.x & 31;
  if (w >= BKT*NP) return;
  int bk = w / NP;
  const float* ctr = g_newxyz + w*3;
  float cx=ctr[0], cy=ctr[1], cz=ctr[2];
  const float R2 = (float)(0.15*0.15);
  int base = w*NS;
  int cnt = 0, first = 0;
  for (int ch = 0; ch < MM/32; ch++){
    int m = ch*32 + lane;
    const float* xp = g_x + (bk*MM + m)*3;
    float d = d2f(cx,cy,cz, xp[0],xp[1],xp[2]);
    unsigned mask = __ballot_sync(0xffffffffu, d < R2);
    if (cnt == 0 && mask) first = ch*32 + __ffs(mask) - 1;
    int pos = cnt + __popc(mask & ((1u<<lane)-1u));
    if ((d < R2) && pos < NS) g_gidx[base + pos] = m;
    cnt += __popc(mask);
    if (cnt >= NS) break;
  }
  for (int j = cnt + lane; j < NS; j += 32) g_gidx[base + j] = first;
}

// ---------------- launch 5: group (mma.sync tf32) ----------------
// smem: H[128][132] | W2[128][132] | W3[128][132]  (floats)  = 202752 B
#define LDW 132
__global__ __launch_bounds__(256, 1) void k_group(float* __restrict__ outFeat){
  extern __shared__ float sm[];
  float* H  = sm;               // [s*LDW + c]
  float* W2 = sm + 128*LDW;
  float* W3 = sm + 2*128*LDW;
  __shared__ int   sIdx[NS];
  __shared__ float sCtr[3];
  __shared__ float sWx[3*128];
  __shared__ float sB1[128], sB2[128];

  int bk = blockIdx.y, p = blockIdx.x, t = threadIdx.x;
  int w = t >> 5, lane = t & 31;
  int gid = lane >> 2, tq = lane & 3;
  int m0 = (w & 3)*32, n0 = (w >> 2)*64;

  int gp_ = bk*NP + p;
  if (t < NS) sIdx[t] = g_gidx[gp_*NS + t];
  if (t < 3)  sCtr[t] = g_newxyz[gp_*3 + t];
  if (t < 128){
    sWx[t]=g_W1x[t]; sWx[128+t]=g_W1x[128+t]; sWx[256+t]=g_W1x[256+t];
    sB1[t]=g_bM1[t]; sB2[t]=g_bM2[t];
  }
  // weights -> smem (stride LDW)
#pragma unroll
  for (int r = 0; r < 16; r++){
    int i = r*256 + t;
    int row = i >> 5, q = i & 31;
    ((float4*)(W2 + row*LDW))[q] = ((const float4*)g_W2T)[i];
    ((float4*)(W3 + row*LDW))[q] = ((const float4*)g_W3T)[i];
  }
  __syncthreads();

  // ---- layer 1 build: H[s][c] tf32-rounded ----
  {
    int s = t >> 1, ob = (t & 1)*64;
    int m = sIdx[s];
    const float* xp = g_x + (bk*MM + m)*3;
    float gx = __fdiv_rn(__fsub_rn(xp[0], sCtr[0]), 0.15f);
    float gy = __fdiv_rn(__fsub_rn(xp[1], sCtr[1]), 0.15f);
    float gz = __fdiv_rn(__fsub_rn(xp[2], sCtr[2]), 0.15f);
    const float4* fp = (const float4*)(g_F1 + ((size_t)bk*MM + m)*128 + ob);
#pragma unroll 4
    for (int j4 = 0; j4 < 16; j4++){
      float4 fv = fp[j4];
      int o = ob + j4*4;
      float4 u;
      u.x = tf32r(fmaxf(fv.x + sWx[o]*gx   + sWx[128+o]*gy   + sWx[256+o]*gz   + sB1[o],   0.f));
      u.y = tf32r(fmaxf(fv.y + sWx[o+1]*gx + sWx[128+o+1]*gy + sWx[256+o+1]*gz + sB1[o+1], 0.f));
      u.z = tf32r(fmaxf(fv.z + sWx[o+2]*gx + sWx[128+o+2]*gy + sWx[256+o+2]*gz + sB1[o+2], 0.f));
      u.w = tf32r(fmaxf(fv.w + sWx[o+3]*gx + sWx[128+o+3]*gy + sWx[256+o+3]*gz + sB1[o+3], 0.f));
      *(float4*)(H + s*LDW + o) = u;
    }
  }
  __syncthreads();

  float acc[2][8][4];
  const u32* Ha = (const u32*)H + (m0 + gid)*LDW + tq;
  const u32* W2a = (const u32*)W2 + (n0 + gid)*LDW + tq;
  const u32* W3a = (const u32*)W3 + (n0 + gid)*LDW + tq;

  // ---- GEMM 1: D1 = H * W2^T ----
#pragma unroll
  for (int mt=0;mt<2;mt++)
#pragma unroll
    for (int nt=0;nt<8;nt++)
#pragma unroll
      for (int j=0;j<4;j++) acc[mt][nt][j] = 0.f;
#pragma unroll 2
  for (int ks = 0; ks < 16; ks++){
    int kc = ks*8;
    u32 a[2][4], b[8][2];
#pragma unroll
    for (int mt = 0; mt < 2; mt++){
      a[mt][0] = Ha[(mt*16)*LDW + kc];
      a[mt][1] = Ha[(mt*16+8)*LDW + kc];
      a[mt][2] = Ha[(mt*16)*LDW + kc + 4];
      a[mt][3] = Ha[(mt*16+8)*LDW + kc + 4];
    }
#pragma unroll
    for (int nt = 0; nt < 8; nt++){
      b[nt][0] = W2a[(nt*8)*LDW + kc];
      b[nt][1] = W2a[(nt*8)*LDW + kc + 4];
    }
#pragma unroll
    for (int mt = 0; mt < 2; mt++)
#pragma unroll
      for (int nt = 0; nt < 8; nt++)
        mma_tf32(acc[mt][nt], a[mt], b[nt]);
  }
  __syncthreads();   // all reads of H done

  // ---- epilogue: H' = tf32(relu(D1 + b2)) ----
#pragma unroll
  for (int mt = 0; mt < 2; mt++){
    int r0 = m0 + mt*16 + gid;
#pragma unroll
    for (int nt = 0; nt < 8; nt++){
      int c0 = n0 + nt*8 + 2*tq;
      float b0v = sB2[c0], b1v = sB2[c0+1];
      float2 v;
      v.x = tf32r(fmaxf(acc[mt][nt][0] + b0v, 0.f));
      v.y = tf32r(fmaxf(acc[mt][nt][1] + b1v, 0.f));
      *(float2*)(H + r0*LDW + c0) = v;
      v.x = tf32r(fmaxf(acc[mt][nt][2] + b0v, 0.f));
      v.y = tf32r(fmaxf(acc[mt][nt][3] + b1v, 0.f));
      *(float2*)(H + (r0+8)*LDW + c0) = v;
    }
  }
  __syncthreads();

  // ---- GEMM 2: D2 = H' * W3^T ----
#pragma unroll
  for (int mt=0;mt<2;mt++)
#pragma unroll
    for (int nt=0;nt<8;nt++)
#pragma unroll
      for (int j=0;j<4;j++) acc[mt][nt][j] = 0.f;
#pragma unroll 2
  for (int ks = 0; ks < 16; ks++){
    int kc = ks*8;
    u32 a[2][4], b[8][2];
#pragma unroll
    for (int mt = 0; mt < 2; mt++){
      a[mt][0] = Ha[(mt*16)*LDW + kc];
      a[mt][1] = Ha[(mt*16+8)*LDW + kc];
      a[mt][2] = Ha[(mt*16)*LDW + kc + 4];
      a[mt][3] = Ha[(mt*16+8)*LDW + kc + 4];
    }
#pragma unroll
    for (int nt = 0; nt < 8; nt++){
      b[nt][0] = W3a[(nt*8)*LDW + kc];
      b[nt][1] = W3a[(nt*8)*LDW + kc + 4];
    }
#pragma unroll
    for (int mt = 0; mt < 2; mt++)
#pragma unroll
      for (int nt = 0; nt < 8; nt++)
        mma_tf32(acc[mt][nt], a[mt], b[nt]);
  }

  // ---- maxpool over s (relu∘max = max∘relu) ----
  float cm[8][2];
#pragma unroll
  for (int nt = 0; nt < 8; nt++){
    cm[nt][0] = fmaxf(fmaxf(acc[0][nt][0], acc[0][nt][2]), fmaxf(acc[1][nt][0], acc[1][nt][2]));
    cm[nt][1] = fmaxf(fmaxf(acc[0][nt][1], acc[0][nt][3]), fmaxf(acc[1][nt][1], acc[1][nt][3]));
  }
#pragma unroll
  for (int off = 4; off < 32; off <<= 1){
#pragma unroll
    for (int nt = 0; nt < 8; nt++){
      cm[nt][0] = fmaxf(cm[nt][0], __shfl_xor_sync(0xffffffffu, cm[nt][0], off));
      cm[nt][1] = fmaxf(cm[nt][1], __shfl_xor_sync(0xffffffffu, cm[nt][1], off));
    }
  }
  float* psm = W2;   // reuse: [4 mwarp][128]
  if (gid == 0){
#pragma unroll
    for (int nt = 0; nt < 8; nt++){
      psm[(w & 3)*128 + n0 + nt*8 + 2*tq]     = cm[nt][0];
      psm[(w & 3)*128 + n0 + nt*8 + 2*tq + 1] = cm[nt][1];
    }
  }
  __syncthreads();
  if (t < 128){
    float mx = fmaxf(fmaxf(psm[t], psm[128+t]), fmaxf(psm[256+t], psm[384+t]));
    float res = fmaxf(mx + g_bM3[t], 0.f);
    int fo = (bk*128 + t)*NP + p;
    g_feat[fo] = res;
    outFeat[fo] = res;
  }
}

// ---------------- launch 6: c1, c2 ----------------
__global__ __launch_bounds__(256) void k_c12(){
  extern __shared__ float sm[];
  float* sH = sm;
  float* sW = sm + 16384;
  int bk = blockIdx.x, t = threadIdx.x;
#pragma unroll
  for (int r = 0; r < 16; r++){
    ((float4*)sH)[r*256 + t] = ((const float4*)(g_feat + bk*16384))[r*256 + t];
    ((float4*)sW)[r*256 + t] = ((const float4*)g_C1T)[r*256 + t];
  }
  __syncthreads();
  int s0 = (t & 15)*8, o0 = (t >> 4)*8;
  u64 acc[8][4]; zacc(acc);
  gemm8x8<128>(sH, sW, acc, s0, o0);
  float2 bb[4];
#pragma unroll
  for (int j = 0; j < 4; j++) bb[j] = *(const float2*)(g_bC1 + o0 + 2*j);
  __syncthreads();
#pragma unroll
  for (int si = 0; si < 8; si++)
#pragma unroll
    for (int j = 0; j < 4; j++){
      float2 v = upk(acc[si][j]);
      sH[(o0+2*j)*128 + s0+si]   = fmaxf(v.x + bb[j].x, 0.f);
      sH[(o0+2*j+1)*128 + s0+si] = fmaxf(v.y + bb[j].y, 0.f);
    }
#pragma unroll
  for (int r = 0; r < 16; r++) ((float4*)sW)[r*256 + t] = ((const float4*)g_C2T)[r*256 + t];
  __syncthreads();
  zacc(acc);
  gemm8x8<128>(sH, sW, acc, s0, o0);
#pragma unroll
  for (int j = 0; j < 4; j++) bb[j] = *(const float2*)(g_bC2 + o0 + 2*j);
  __syncthreads();
#pragma unroll
  for (int si = 0; si < 8; si++)
#pragma unroll
    for (int j = 0; j < 4; j++){
      float2 v = upk(acc[si][j]);
      sH[(o0+2*j)*128 + s0+si]   = fmaxf(v.x + bb[j].x, 0.f);
      sH[(o0+2*j+1)*128 + s0+si] = fmaxf(v.y + bb[j].y, 0.f);
    }
  __syncthreads();
#pragma unroll
  for (int r = 0; r < 16; r++) ((float4*)(g_net + bk*16384))[r*256 + t] = ((const float4*)sH)[r*256 + t];
}

// ---------------- launch 7: head ----------------
__global__ void k_head(const float* __restrict__ opw, const float* __restrict__ opb,
                       float* __restrict__ outScores){
  __shared__ float sOp[5*128]; __shared__ float sOb[5];
  int bk = blockIdx.x, k = bk % KK, t = threadIdx.x;
  for (int i = t; i < 640; i += 128) sOp[i] = opw[k*640 + i];
  if (t < 5) sOb[t] = opb[k*5 + t];
  __syncthreads();
  float a0=0,a1=0,a2=0,a3=0,a4=0;
  const float* nb = g_net + bk*16384 + t;
#pragma unroll 4
  for (int c = 0; c < 128; c++){
    float nv = nb[c*128];
    a0 += sOp[c]*nv; a1 += sOp[128+c]*nv; a2 += sOp[256+c]*nv; a3 += sOp[384+c]*nv; a4 += sOp[512+c]*nv;
  }
  a0+=sOb[0]; a1+=sOb[1]; a2+=sOb[2]; a3+=sOb[3]; a4+=sOb[4];
  const float* nz = g_newxyz + (bk*NP + t)*3;
  float* o = outScores + (bk*NP + t)*5;
  o[0]=a0; o[1]=a1; o[2]=nz[0]+a2; o[3]=nz[1]+a3; o[4]=nz[2]+a4;
}

// ---------------- launcher ----------------
extern "C" void kernel_launch(void* const* d_in, const int* in_sizes, int n_in,
                              void* d_out, int out_size){
  (void)in_sizes; (void)n_in; (void)out_size;
  const float* xyz  = (const float*)d_in[0];
  const float* feats= (const float*)d_in[1];
  const float* m1_w = (const float*)d_in[2];
  const float* m1_b = (const float*)d_in[3];
  const float* m1_g = (const float*)d_in[4];
  const float* m1_be= (const float*)d_in[5];
  const float* m2_w = (const float*)d_in[6];
  const float* m2_b = (const float*)d_in[7];
  const float* m2_g = (const float*)d_in[8];
  const float* m2_be= (const float*)d_in[9];
  const float* m3_w = (const float*)d_in[10];
  const float* m3_b = (const float*)d_in[11];
  const float* m3_g = (const float*)d_in[12];
  const float* m3_be= (const float*)d_in[13];
  const float* c1_w = (const float*)d_in[14];
  const float* c1_b = (const float*)d_in[15];
  const float* c1_g = (const float*)d_in[16];
  const float* c1_be= (const float*)d_in[17];
  const float* c2_w = (const float*)d_in[18];
  const float* c2_b = (const float*)d_in[19];
  const float* c2_g = (const float*)d_in[20];
  const float* c2_be= (const float*)d_in[21];
  const float* op_w = (const float*)d_in[22];
  const float* op_b = (const float*)d_in[23];

  float* out = (float*)d_out;
  float* outScores = out;                 // 38*128*5
  float* outAgg    = out + 24320;         // 38*128*3
  float* outFeat   = out + 38912;         // 38*128*128

  cudaFuncSetAttribute(k_f1,    cudaFuncAttributeMaxDynamicSharedMemorySize, 65536);
  cudaFuncSetAttribute(k_group, cudaFuncAttributeMaxDynamicSharedMemorySize, 202752);
  cudaFuncSetAttribute(k_c12,   cudaFuncAttributeMaxDynamicSharedMemorySize, 131072);

  k_prep_x<<<(BKT*MM*3 + 255)/256, 256>>>(xyz);                        // 0
  k_fold_all<<<(99328 + 255)/256, 256>>>(m1_w, m1_g, m2_w, m2_g,       // 1
      m3_w, m3_g, c1_w, c1_g, c2_w, c2_g,
      m1_b, m1_be, m2_b, m2_be, m3_b, m3_be, c1_b, c1_be, c2_b, c2_be);
  k_fps<<<BKT, 1024>>>(outAgg);                                        // 2
  k_f1<<<dim3(MM/128, BKT), 256, 65536>>>(feats);                      // 3
  k_ball<<<(BKT*NP*32 + 255)/256, 256>>>();                            // 4
  k_group<<<dim3(NP, BKT), 256, 202752>>>(outFeat);                    // 5 <- profiled
  k_c12<<<BKT, 256, 131072>>>();                                       // 6
  k_head<<<BKT, 128>>>(op_w, op_b, outScores);                         // 7
}